// round 12
// baseline (speedup 1.0000x reference)
#include <cuda_runtime.h>
#include <cuda_fp16.h>
#include <stdint.h>
#include <math.h>

#define B_    128
#define N_    196
#define ENC_  2048
#define DEC_  512
#define ATT_  512
#define M_    (B_ * N_)          // 25088 rows
#define KF_TOT (ENC_ / 16)       // 128 k16 fragments
#define FN_TOT (ATT_ / 8)        // 64  n8 fragments

// gemm tiling: block 128m x 128n x 64k, 2-stage, 2 CTAs/SM  (R8 dataflow, FROZEN)
#define NKS        32            // k-steps of 64
#define STAGE_U32  12288         // 48KB per stage
#define SMEM_BYTES (2 * STAGE_U32 * 4)   // 98304

// ---- scratch (__device__ globals: sanctioned no-alloc workaround) ----
__device__ float    g_att2[B_ * ATT_];
__device__ float    g_epart[M_ * 4];
__device__ uint32_t g_Bf[FN_TOT * KF_TOT * 64];   // B fp16 frag-major, permuted k

// ============================================================
// helpers
// ============================================================
__device__ __forceinline__ uint32_t pack_h2(__half lo, __half hi) {
    __half2 p; p.x = lo; p.y = hi;       // .x = low 16 bits (lower k index)
    return *reinterpret_cast<uint32_t*>(&p);
}
__device__ __forceinline__ uint32_t cvt2h(float hi, float lo) {
    uint32_t r;
    asm("cvt.rn.f16x2.f32 %0, %1, %2;" : "=r"(r) : "f"(hi), "f"(lo));
    return r;
}
__device__ __forceinline__ void cp16(uint32_t saddr, const void* g) {
    asm volatile("cp.async.cg.shared.global [%0], [%1], 16;\n" :: "r"(saddr), "l"(g));
}
__device__ __forceinline__ void cp_commit() { asm volatile("cp.async.commit_group;\n"); }
template <int NN> __device__ __forceinline__ void cp_wait() {
    asm volatile("cp.async.wait_group %0;\n" :: "n"(NN));
}
__device__ __forceinline__ void mma16816(float c[4], const uint32_t a[4], const uint32_t b[2]) {
    asm volatile(
        "mma.sync.aligned.m16n8k16.row.col.f32.f16.f16.f32 "
        "{%0,%1,%2,%3}, {%4,%5,%6,%7}, {%8,%9}, {%0,%1,%2,%3};\n"
        : "+f"(c[0]), "+f"(c[1]), "+f"(c[2]), "+f"(c[3])
        : "r"(a[0]), "r"(a[1]), "r"(a[2]), "r"(a[3]),
          "r"(b[0]), "r"(b[1]));
}

// ============================================================
// Kernel 1 (fused prep): blocks 0..127 -> att2; blocks 128..1151 -> prepackB
//   att2[b][a] = decoder_hidden[b] . W_dec[:,a] + b_dec[a]     (fp32 exact)
//   prepackB: W_enc [K][N] -> fp16 frag-major, PERMUTED k layout
//     position (tig, kreg, elem) holds k = kf*16 + tig*4 + kreg*2 + elem
// ============================================================
__global__ __launch_bounds__(512)
void prep_kernel(const float* __restrict__ dec,
                 const float* __restrict__ Wdec,
                 const float* __restrict__ bdec,
                 const float* __restrict__ Wenc) {
    __shared__ float ds[DEC_];
    if (blockIdx.x < 128) {
        int b = blockIdx.x, a = threadIdx.x;       // 512 threads
        ds[a] = dec[b * DEC_ + a];
        __syncthreads();
        float acc = bdec[a];
#pragma unroll 8
        for (int d = 0; d < DEC_; d++) acc += ds[d] * Wdec[d * ATT_ + a];
        g_att2[b * ATT_ + a] = acc;
    } else {
        int idx = (blockIdx.x - 128) * 512 + threadIdx.x;   // < 524288
        int reg  = idx & 1;                  // kreg
        int lane = (idx >> 1) & 31;
        int kf   = (idx >> 6) & (KF_TOT - 1);
        int fn   = idx >> 13;
        int n = fn * 8 + (lane >> 2);
        int k = kf * 16 + (lane & 3) * 4 + reg * 2;   // permuted
        float v0 = Wenc[(size_t)k * ATT_ + n];
        float v1 = Wenc[(size_t)(k + 1) * ATT_ + n];
        g_Bf[idx] = pack_h2(__float2half_rn(v0), __float2half_rn(v1));
    }
}

// ============================================================
// Kernel 2: HMMA GEMM (1-term fp16, A converted in-kernel) + epilogue
//   == exact R8/R11 dataflow (measured ~160us) — FROZEN ==
// ============================================================
__global__ __launch_bounds__(256, 2)
void gemm_e_kernel(const float* __restrict__ enc,
                   const float* __restrict__ benc,
                   const float* __restrict__ Wfull) {
    extern __shared__ uint32_t sm[];   // 2 stages x 12288 u32
    const int tid = threadIdx.x;
    const int lane = tid & 31, wid = tid >> 5;
    const int warpM = wid & 3, warpN = wid >> 2;   // 4M x 2N
    const int nchunk = blockIdx.x;     // 0..3
    const int mtile  = blockIdx.y;     // 0..195
    const int m0g = mtile * 128;
    const int g = lane >> 2, tig = lane & 3;

    const uint32_t smbase = (uint32_t)__cvta_generic_to_shared(sm);

    float acc[2][8][4];
#pragma unroll
    for (int i = 0; i < 2; i++)
#pragma unroll
        for (int j = 0; j < 8; j++)
#pragma unroll
            for (int q = 0; q < 4; q++) acc[i][j][q] = 0.f;

    // ---- async load of k-step ks (64 k): A raw fp32 + B fp16; 12/thread ----
    auto issue = [&](int ks, int st) {
        const uint32_t so = smbase + (uint32_t)(st * STAGE_U32) * 4u;
#pragma unroll
        for (int i = 0; i < 12; i++) {
            int c = i * 256 + tid;           // 0..3071
            uint32_t dst;
            const void* src;
            if (c < 2048) {                  // A: row(128) x chunk16(16B=4 fp32)
                int row = c >> 4, cc = c & 15;
                int csw = (cc + row * 4) & 15;
                src = enc + (size_t)(m0g + row) * ENC_ + ks * 64 + cc * 4;
                dst = so + (uint32_t)(row * 64 + csw * 4) * 4u;
            } else {                         // B: fn16 kf4 q16
                int d = c - 2048;
                int fn = d >> 6, kf = (d >> 4) & 3, q = d & 15;
                src = g_Bf + ((size_t)(nchunk * 16 + fn) * KF_TOT + (ks * 4 + kf)) * 64 + q * 4;
                dst = so + (uint32_t)(8192 + (fn * 4 + kf) * 64 + q * 4) * 4u;
            }
            cp16(dst, src);
        }
        cp_commit();
    };

    issue(0, 0);

    for (int s = 0; s < NKS; s++) {
        const int st = s & 1;
        cp_wait<0>();                 // only group s outstanding here
        __syncthreads();              // all warps done reading buffer s-1
        if (s + 1 < NKS) issue(s + 1, st ^ 1);

        const int sb = st * STAGE_U32;
#pragma unroll
        for (int kf = 0; kf < 4; kf++) {
            // A fragments: 2x LDS.128 fp32 + 4 cvt per fm
            uint32_t a[2][4];
#pragma unroll
            for (int fm = 0; fm < 2; fm++) {
                int rbase = (warpM * 2 + fm) * 16;
                int r0 = rbase + g, r1 = rbase + 8 + g;
                int c0 = ((kf * 4 + tig) + r0 * 4) & 15;
                int c1 = ((kf * 4 + tig) + r1 * 4) & 15;
                float4 f0 = *reinterpret_cast<const float4*>(&sm[sb + r0 * 64 + c0 * 4]);
                float4 f1 = *reinterpret_cast<const float4*>(&sm[sb + r1 * 64 + c1 * 4]);
                a[fm][0] = cvt2h(f0.y, f0.x);
                a[fm][1] = cvt2h(f1.y, f1.x);
                a[fm][2] = cvt2h(f0.w, f0.z);
                a[fm][3] = cvt2h(f1.w, f1.z);
            }
            // B fragments: one LDS.64 per fn
            uint32_t b[8][2];
#pragma unroll
            for (int fn = 0; fn < 8; fn++) {
                int fnAbs = warpN * 8 + fn;
                uint2 v = *reinterpret_cast<const uint2*>(
                    &sm[sb + 8192 + (fnAbs * 4 + kf) * 64 + lane * 2]);
                b[fn][0] = v.x; b[fn][1] = v.y;
            }
#pragma unroll
            for (int fm = 0; fm < 2; fm++)
#pragma unroll
                for (int fn = 0; fn < 8; fn++)
                    mma16816(acc[fm][fn], a[fm], b[fn]);
        }
    }

    // ---- fused epilogue: v = relu(acc + b_enc + att2); e += v * W_full ----
    float ep[2][2] = {{0.f, 0.f}, {0.f, 0.f}};
#pragma unroll
    for (int fm = 0; fm < 2; fm++) {
        int r0 = warpM * 32 + fm * 16 + g;
        int b0 = (m0g + r0) / N_;
        int b1 = (m0g + r0 + 8) / N_;
#pragma unroll
        for (int fn = 0; fn < 8; fn++) {
            int a0i = nchunk * 128 + warpN * 64 + fn * 8 + tig * 2;
            int a1i = a0i + 1;
            float w0 = Wfull[a0i], w1 = Wfull[a1i];
            float be0 = benc[a0i], be1 = benc[a1i];
            float t00 = g_att2[b0 * ATT_ + a0i];
            float t01 = g_att2[b0 * ATT_ + a1i];
            float t10 = g_att2[b1 * ATT_ + a0i];
            float t11 = g_att2[b1 * ATT_ + a1i];
            ep[fm][0] += fmaxf(acc[fm][fn][0] + be0 + t00, 0.f) * w0;
            ep[fm][0] += fmaxf(acc[fm][fn][1] + be1 + t01, 0.f) * w1;
            ep[fm][1] += fmaxf(acc[fm][fn][2] + be0 + t10, 0.f) * w0;
            ep[fm][1] += fmaxf(acc[fm][fn][3] + be1 + t11, 0.f) * w1;
        }
    }
#pragma unroll
    for (int off = 1; off <= 2; off <<= 1)
#pragma unroll
        for (int fm = 0; fm < 2; fm++) {
            ep[fm][0] += __shfl_xor_sync(0xffffffffu, ep[fm][0], off);
            ep[fm][1] += __shfl_xor_sync(0xffffffffu, ep[fm][1], off);
        }

    __syncthreads();
    float* e_red = reinterpret_cast<float*>(sm);  // [128][2]
    if (tig == 0) {
#pragma unroll
        for (int fm = 0; fm < 2; fm++) {
            int r0 = warpM * 32 + fm * 16 + g;
            e_red[r0 * 2 + warpN]       = ep[fm][0];
            e_red[(r0 + 8) * 2 + warpN] = ep[fm][1];
        }
    }
    __syncthreads();
    if (tid < 128)
        g_epart[(size_t)(m0g + tid) * 4 + nchunk] = e_red[tid * 2] + e_red[tid * 2 + 1];
}

// ============================================================
// Kernel 3: fused softmax + awe
//   grid (2, B): block recomputes softmax for its b; x==0 writes alpha.
//   awe: 7 chains, 2-deep batched loads -> 14 LDG.128 in flight
// ============================================================
__global__ void awe_kernel(const float* __restrict__ enc,
                           const float* __restrict__ bfull_p,
                           float* __restrict__ out_alpha,
                           float* __restrict__ out_awe) {
    __shared__ float al[N_];
    __shared__ float red[256];
    int b = blockIdx.y, tid = threadIdx.x;
    float bfull = *bfull_p;

    // ---- softmax over n (196) ----
    float ev = -INFINITY;
    float sval = 0.f;
    if (tid < N_) {
        const float* p = &g_epart[(size_t)(b * N_ + tid) * 4];
        sval = bfull + p[0] + p[1] + p[2] + p[3];
        ev = sval;
    }
    red[tid] = ev; __syncthreads();
#pragma unroll
    for (int off = 128; off > 0; off >>= 1) {
        if (tid < off) red[tid] = fmaxf(red[tid], red[tid + off]);
        __syncthreads();
    }
    float mx = red[0]; __syncthreads();
    float ex = 0.f;
    if (tid < N_) ex = expf(sval - mx);
    red[tid] = ex; __syncthreads();
#pragma unroll
    for (int off = 128; off > 0; off >>= 1) {
        if (tid < off) red[tid] += red[tid + off];
        __syncthreads();
    }
    float inv = 1.f / red[0];
    if (tid < N_) {
        float a = ex * inv;
        al[tid] = a;
        if (blockIdx.x == 0) out_alpha[b * N_ + tid] = a;
    }
    __syncthreads();

    // ---- weighted encoding: 7 chains (196 = 7*28), 2-deep load batches ----
    int e0 = (blockIdx.x * 256 + tid) * 4;
    const float4* p = reinterpret_cast<const float4*>(enc + (size_t)b * N_ * ENC_ + e0);
    float4 acc[7];
#pragma unroll
    for (int c = 0; c < 7; c++) acc[c] = make_float4(0.f, 0.f, 0.f, 0.f);

#pragma unroll 1
    for (int n = 0; n < 28; n += 2) {
        float4 v[7], u[7];
#pragma unroll
        for (int c = 0; c < 7; c++)
            v[c] = p[(size_t)(n + c * 28) * (ENC_ / 4)];
#pragma unroll
        for (int c = 0; c < 7; c++)
            u[c] = p[(size_t)(n + 1 + c * 28) * (ENC_ / 4)];
#pragma unroll
        for (int c = 0; c < 7; c++) {
            float w = al[n + c * 28];
            acc[c].x += w * v[c].x; acc[c].y += w * v[c].y;
            acc[c].z += w * v[c].z; acc[c].w += w * v[c].w;
        }
#pragma unroll
        for (int c = 0; c < 7; c++) {
            float w = al[n + 1 + c * 28];
            acc[c].x += w * u[c].x; acc[c].y += w * u[c].y;
            acc[c].z += w * u[c].z; acc[c].w += w * u[c].w;
        }
    }
    float4 r;
    r.x = ((acc[0].x + acc[1].x) + (acc[2].x + acc[3].x)) + ((acc[4].x + acc[5].x) + acc[6].x);
    r.y = ((acc[0].y + acc[1].y) + (acc[2].y + acc[3].y)) + ((acc[4].y + acc[5].y) + acc[6].y);
    r.z = ((acc[0].z + acc[1].z) + (acc[2].z + acc[3].z)) + ((acc[4].z + acc[5].z) + acc[6].z);
    r.w = ((acc[0].w + acc[1].w) + (acc[2].w + acc[3].w)) + ((acc[4].w + acc[5].w) + acc[6].w);
    *reinterpret_cast<float4*>(out_awe + (size_t)b * ENC_ + e0) = r;
}

// ============================================================
extern "C" void kernel_launch(void* const* d_in, const int* in_sizes, int n_in,
                              void* d_out, int out_size) {
    const float* enc   = (const float*)d_in[0];
    const float* dech  = (const float*)d_in[1];
    const float* Wenc  = (const float*)d_in[2];
    const float* benc  = (const float*)d_in[3];
    const float* Wdec  = (const float*)d_in[4];
    const float* bdec  = (const float*)d_in[5];
    const float* Wfull = (const float*)d_in[6];
    const float* bfull = (const float*)d_in[7];

    float* out       = (float*)d_out;
    float* out_awe   = out;
    float* out_alpha = out + (size_t)B_ * ENC_;

    cudaFuncSetAttribute(gemm_e_kernel,
                         cudaFuncAttributeMaxDynamicSharedMemorySize, SMEM_BYTES);

    // fused att2 + prepackB: 128 att2 blocks + 1024 prepackB blocks
    prep_kernel<<<128 + 1024, 512>>>(dech, Wdec, bdec, Wenc);

    dim3 g2(4, 196);                           // nchunk fastest -> A L2 reuse
    gemm_e_kernel<<<g2, 256, SMEM_BYTES>>>(enc, benc, Wfull);

    dim3 g3(2, B_);
    awe_kernel<<<g3, 256>>>(enc, bfull, out_alpha, out_awe);
}